// round 8
// baseline (speedup 1.0000x reference)
#include <cuda_runtime.h>
#include <cuda_bf16.h>
#include <math.h>
#include <stdint.h>

// Problem dims
#define BB 256
#define TT 512
#define CHD 1024
#define LHD 1024
#define SSS 16
#define NNN 16
#define SB 4096            // S*B rows of decoder state
#define KW 1536            // T + LH

// ---------------- scratch (device globals) ----------------------------------
__device__ float g_decin[SB * 2 * LHD];             // 32MB
__device__ float g_prectx[SB * 4 * LHD];            // 64MB (permuted cols, bias folded)
__device__ float g_dc[SB * LHD];                    // c state (cond uses rows 0..255)
__device__ float g_pbdec[4 * LHD];                  // permuted dec bias (bih+bhh)
__device__ float g_pbcond[4 * CHD];                 // permuted cond bias
__device__ __nv_bfloat16 g_h0hi[SB * LHD], g_h0lo[SB * LHD];   // h ping
__device__ __nv_bfloat16 g_h1hi[SB * LHD], g_h1lo[SB * LHD];   // h pong
__device__ __nv_bfloat16 g_whi[4 * LHD * KW],  g_wlo[4 * LHD * KW];    // [Wtok|Whh] permuted rows
__device__ __nv_bfloat16 g_xhi[BB * SSS * NNN * TT], g_xlo[BB * SSS * NNN * TT];
__device__ __nv_bfloat16 g_cwhi[4 * CHD * CHD], g_cwlo[4 * CHD * CHD]; // cond_Whh permuted rows
__device__ __nv_bfloat16 g_wctxhi[4 * LHD * 2 * LHD], g_wctxlo[4 * LHD * 2 * LHD]; // permuted rows
__device__ __nv_bfloat16 g_owhi[TT * LHD], g_owlo[TT * LHD];
__device__ __nv_bfloat16 g_pwhi[2 * LHD * CHD], g_pwlo[2 * LHD * CHD];
__device__ __nv_bfloat16 g_cohi[SSS * BB * CHD], g_colo[SSS * BB * CHD];   // cond outs
__device__ __nv_bfloat16 g_dinhi[SB * 2 * LHD], g_dinlo[SB * 2 * LHD];
__device__ __nv_bfloat16 g_histhi[NNN * SB * LHD], g_histlo[NNN * SB * LHD]; // 134MB x2

__device__ __forceinline__ float sigm(float x) { return 1.0f / (1.0f + expf(-x)); }
__device__ __forceinline__ void split_bf(float v, __nv_bfloat16& hi, __nv_bfloat16& lo) {
    hi = __float2bfloat16(v);
    lo = __float2bfloat16(v - __bfloat162float(hi));
}

// ==================== PTX helpers (sm_80-portable only) =====================
__device__ __forceinline__ uint32_t smem_u32(const void* p) {
    uint32_t a;
    asm("{ .reg .u64 t; cvta.to.shared.u64 t, %1; cvt.u32.u64 %0, t; }" : "=r"(a) : "l"(p));
    return a;
}
__device__ __forceinline__ void cp16(uint32_t d, const void* s) {
    asm volatile("cp.async.cg.shared.global [%0], [%1], 16;" :: "r"(d), "l"(s));
}
__device__ __forceinline__ void cp_commit() {
    asm volatile("cp.async.commit_group;" ::: "memory");
}
__device__ __forceinline__ void cp_wait2() {
    asm volatile("cp.async.wait_group 2;" ::: "memory");
}
__device__ __forceinline__ void ldsm4(uint32_t* r, uint32_t addr) {
    asm volatile("ldmatrix.sync.aligned.m8n8.x4.shared.b16 {%0,%1,%2,%3}, [%4];"
                 : "=r"(r[0]), "=r"(r[1]), "=r"(r[2]), "=r"(r[3]) : "r"(addr));
}
__device__ __forceinline__ void mma16816(float* c, const uint32_t* a, uint32_t b0, uint32_t b1) {
    asm volatile(
        "mma.sync.aligned.m16n8k16.row.col.f32.bf16.bf16.f32 "
        "{%0,%1,%2,%3}, {%4,%5,%6,%7}, {%8,%9}, {%0,%1,%2,%3};"
        : "+f"(c[0]), "+f"(c[1]), "+f"(c[2]), "+f"(c[3])
        : "r"(a[0]), "r"(a[1]), "r"(a[2]), "r"(a[3]), "r"(b0), "r"(b1));
}

#define RSTRIDE 40
#define STAGE_B 20480
#define NSTAGE 4

// =================== fused gates-GEMM + LSTM cell ===========================
// gates = A @ B^T (3-pass bf16 split), epilogue applies LSTM cell with
// gate-permuted column layout: col = cb*64 + gate*16 + u4, unit = cb*16+u4.
__global__ void __launch_bounds__(256) gemm_lstm_kernel(
    int n, int K, int use_tok,
    const __nv_bfloat16* __restrict__ Ahi, const __nv_bfloat16* __restrict__ Alo,
    const __nv_bfloat16* __restrict__ Bhi, const __nv_bfloat16* __restrict__ Blo, int ldb,
    const float* __restrict__ pre,     // nullable: prectx(+bias), ld 4096, permuted cols
    const float* __restrict__ pbias,   // nullable: permuted combined bias
    float* __restrict__ cst,
    __nv_bfloat16* __restrict__ Hhi, __nv_bfloat16* __restrict__ Hlo,
    __nv_bfloat16* __restrict__ histhi, __nv_bfloat16* __restrict__ histlo, int hist_off)
{
    extern __shared__ char smem[];
    const uint32_t sb = smem_u32(smem);
    const int tid  = threadIdx.x;
    const int lane = tid & 31;
    const int wid  = tid >> 5;
    const int mbase = blockIdx.y * 128;
    const int nbase = blockIdx.x * 128;
    const int wm = (wid & 3) * 32;
    const int wn = (wid >> 2) * 64;

    const int cpp = K / 32;
    const int NK  = 3 * cpp;
    const int hoff = use_tok ? 512 : 0;

    const int lrow = tid >> 2;
    const int lc   = tid & 3;

    const int t8 = lane >> 3;
    const int r8 = lane & 7;
    const uint32_t a_lane = (uint32_t)((wm + (t8 & 1) * 8 + r8) * (RSTRIDE * 2) + (t8 >> 1) * 16);
    const uint32_t b_lane = (uint32_t)(10240 + (wn + (t8 >> 1) * 8 + r8) * (RSTRIDE * 2) + (t8 & 1) * 16);

    float acc[2][8][4];
#pragma unroll
    for (int i = 0; i < 2; i++)
#pragma unroll
        for (int j = 0; j < 8; j++)
#pragma unroll
            for (int v = 0; v < 4; v++) acc[i][j][v] = 0.0f;

    auto load_chunk = [&](int kt) {
        const int slot = kt - (kt / NSTAGE) * NSTAGE;
        const int pass = kt / cpp;
        const int kk = (kt - pass * cpp) * 32;
        const __nv_bfloat16* hsrc = (pass == 2) ? Alo : Ahi;
        const __nv_bfloat16* xsrc = (pass == 2) ? g_xlo : g_xhi;
        const __nv_bfloat16* wsrc = (pass == 1) ? Blo : Bhi;
        const uint32_t a_s = sb + slot * STAGE_B;
        const uint32_t b_s = a_s + 10240;
        int row = lrow;
#pragma unroll
        for (int it = 0; it < 2; it++, row += 64) {
            const void* src;
            if (use_tok && kk < 512) {
                const int m = mbase + row, b = m & 255, s = m >> 8;
                src = xsrc + ((size_t)(b * (SSS * NNN) + s * NNN + n - 1)) * TT + kk + lc * 8;
            } else {
                src = hsrc + (size_t)(mbase + row) * LHD + (kk - hoff) + lc * 8;
            }
            cp16(a_s + row * (RSTRIDE * 2) + lc * 16, src);
        }
        row = lrow;
#pragma unroll
        for (int it = 0; it < 2; it++, row += 64) {
            const void* src = wsrc + (size_t)(nbase + row) * ldb + kk + lc * 8;
            cp16(b_s + row * (RSTRIDE * 2) + lc * 16, src);
        }
    };

    for (int c = 0; c < 3; c++) { load_chunk(c); cp_commit(); }

    for (int kt = 0; kt < NK; kt++) {
        const int slot = kt - (kt / NSTAGE) * NSTAGE;
        cp_wait2();
        __syncthreads();
        const uint32_t stage = sb + slot * STAGE_B;
#pragma unroll
        for (int ks = 0; ks < 2; ks++) {
            uint32_t a[2][4], b[4][4];
#pragma unroll
            for (int mi = 0; mi < 2; mi++)
                ldsm4(a[mi], stage + a_lane + mi * 16 * (RSTRIDE * 2) + ks * 32);
#pragma unroll
            for (int bi = 0; bi < 4; bi++)
                ldsm4(b[bi], stage + b_lane + bi * 16 * (RSTRIDE * 2) + ks * 32);
#pragma unroll
            for (int mi = 0; mi < 2; mi++)
#pragma unroll
                for (int ni = 0; ni < 8; ni++)
                    mma16816(acc[mi][ni], a[mi], b[ni >> 1][(ni & 1) * 2], b[ni >> 1][(ni & 1) * 2 + 1]);
        }
        const int pf = kt + 3;
        if (pf < NK) load_chunk(pf);
        cp_commit();
    }

    // -------- fused LSTM cell epilogue --------
    const int cb = (nbase + wn) >> 6;       // 64-col gate block
    const int cpair = (lane & 3) * 2;
#pragma unroll
    for (int mi = 0; mi < 2; mi++) {
        const int row0 = mbase + wm + mi * 16 + (lane >> 2);
#pragma unroll
        for (int g2 = 0; g2 < 2; g2++) {
#pragma unroll
            for (int v = 0; v < 4; v++) {
                const int r = row0 + (v >> 1) * 8;
                const int cloc = (v & 1);    // col within pair
                float gi, gf, gg, go;
                if (pre) {
                    const float* pr = pre + (size_t)r * 4096 + nbase + wn + cpair + cloc;
                    gi = acc[mi][g2][v]     + pr[(g2)     * 8];
                    gf = acc[mi][g2 + 2][v] + pr[(g2 + 2) * 8];
                    gg = acc[mi][g2 + 4][v] + pr[(g2 + 4) * 8];
                    go = acc[mi][g2 + 6][v] + pr[(g2 + 6) * 8];
                } else {
                    const float* pb = pbias + nbase + wn + cpair + cloc;
                    gi = acc[mi][g2][v]     + pb[(g2)     * 8];
                    gf = acc[mi][g2 + 2][v] + pb[(g2 + 2) * 8];
                    gg = acc[mi][g2 + 4][v] + pb[(g2 + 4) * 8];
                    go = acc[mi][g2 + 6][v] + pb[(g2 + 6) * 8];
                }
                const int unit = cb * 16 + g2 * 8 + cpair + cloc;
                const size_t ci = (size_t)r * 1024 + unit;
                float cn = sigm(gf) * cst[ci] + sigm(gi) * tanhf(gg);
                float hn = sigm(go) * tanhf(cn);
                cst[ci] = cn;
                __nv_bfloat16 hi, lo; split_bf(hn, hi, lo);
                Hhi[ci] = hi; Hlo[ci] = lo;
                if (histhi) {
                    const size_t hx = (size_t)(hist_off + r) * 1024 + unit;
                    histhi[hx] = hi; histlo[hx] = lo;
                }
            }
        }
    }
}

// ==================== generic 3-pass split mma GEMM =========================
// out_mode 0: linear C[M,ldc]; 2: scatter rows (n,s,b) to harness output.
__global__ void __launch_bounds__(256) gemm3_kernel(
    const __nv_bfloat16* __restrict__ Ahi, const __nv_bfloat16* __restrict__ Alo, int lda,
    const __nv_bfloat16* __restrict__ Bhi, const __nv_bfloat16* __restrict__ Blo, int ldb,
    float* __restrict__ C, int ldc, int K,
    const float* __restrict__ bias, int out_mode)
{
    extern __shared__ char smem[];
    const uint32_t sb = smem_u32(smem);
    const int tid  = threadIdx.x;
    const int lane = tid & 31;
    const int wid  = tid >> 5;
    const int mbase = blockIdx.y * 128;
    const int nbase = blockIdx.x * 128;
    const int wm = (wid & 3) * 32;
    const int wn = (wid >> 2) * 64;

    const int cpp = K / 32;
    const int NK  = 3 * cpp;

    const int lrow = tid >> 2;
    const int lc   = tid & 3;

    const int t8 = lane >> 3;
    const int r8 = lane & 7;
    const uint32_t a_lane = (uint32_t)((wm + (t8 & 1) * 8 + r8) * (RSTRIDE * 2) + (t8 >> 1) * 16);
    const uint32_t b_lane = (uint32_t)(10240 + (wn + (t8 >> 1) * 8 + r8) * (RSTRIDE * 2) + (t8 & 1) * 16);

    float acc[2][8][4];
#pragma unroll
    for (int i = 0; i < 2; i++)
#pragma unroll
        for (int j = 0; j < 8; j++)
#pragma unroll
            for (int v = 0; v < 4; v++) acc[i][j][v] = 0.0f;

    auto load_chunk = [&](int kt) {
        const int slot = kt - (kt / NSTAGE) * NSTAGE;
        const int pass = kt / cpp;
        const int kk = (kt - pass * cpp) * 32;
        const __nv_bfloat16* As = (pass == 2) ? Alo : Ahi;
        const __nv_bfloat16* Bs = (pass == 1) ? Blo : Bhi;
        const uint32_t a_s = sb + slot * STAGE_B;
        const uint32_t b_s = a_s + 10240;
        int row = lrow;
#pragma unroll
        for (int it = 0; it < 2; it++, row += 64) {
            cp16(a_s + row * (RSTRIDE * 2) + lc * 16,
                 As + (size_t)(mbase + row) * lda + kk + lc * 8);
        }
        row = lrow;
#pragma unroll
        for (int it = 0; it < 2; it++, row += 64) {
            cp16(b_s + row * (RSTRIDE * 2) + lc * 16,
                 Bs + (size_t)(nbase + row) * ldb + kk + lc * 8);
        }
    };

    for (int c = 0; c < 3; c++) { load_chunk(c); cp_commit(); }

    for (int kt = 0; kt < NK; kt++) {
        const int slot = kt - (kt / NSTAGE) * NSTAGE;
        cp_wait2();
        __syncthreads();
        const uint32_t stage = sb + slot * STAGE_B;
#pragma unroll
        for (int ks = 0; ks < 2; ks++) {
            uint32_t a[2][4], b[4][4];
#pragma unroll
            for (int mi = 0; mi < 2; mi++)
                ldsm4(a[mi], stage + a_lane + mi * 16 * (RSTRIDE * 2) + ks * 32);
#pragma unroll
            for (int bi = 0; bi < 4; bi++)
                ldsm4(b[bi], stage + b_lane + bi * 16 * (RSTRIDE * 2) + ks * 32);
#pragma unroll
            for (int mi = 0; mi < 2; mi++)
#pragma unroll
                for (int ni = 0; ni < 8; ni++)
                    mma16816(acc[mi][ni], a[mi], b[ni >> 1][(ni & 1) * 2], b[ni >> 1][(ni & 1) * 2 + 1]);
        }
        const int pf = kt + 3;
        if (pf < NK) load_chunk(pf);
        cp_commit();
    }

    const int col0 = nbase + wn + (lane & 3) * 2;
#pragma unroll
    for (int mi = 0; mi < 2; mi++) {
        const int row0 = mbase + wm + mi * 16 + (lane >> 2);
#pragma unroll
        for (int ni = 0; ni < 8; ni++) {
            const int col = col0 + ni * 8;
            float b0 = 0.f, b1 = 0.f;
            if (bias) { b0 = bias[col]; b1 = bias[col + 1]; }
            float *p0, *p1;
            if (out_mode == 2) {
                int r0 = row0;
                int nn = r0 >> 12, ss = (r0 >> 8) & 15, bb = r0 & 255;
                p0 = C + ((size_t)bb * (SSS * NNN) + (size_t)(ss * NNN + nn)) * TT + col;
                int r1 = row0 + 8;
                nn = r1 >> 12; ss = (r1 >> 8) & 15; bb = r1 & 255;
                p1 = C + ((size_t)bb * (SSS * NNN) + (size_t)(ss * NNN + nn)) * TT + col;
            } else {
                p0 = C + (size_t)row0 * ldc + col;
                p1 = p0 + (size_t)8 * ldc;
            }
            *(float2*)p0 = make_float2(acc[mi][ni][0] + b0, acc[mi][ni][1] + b1);
            *(float2*)p1 = make_float2(acc[mi][ni][2] + b0, acc[mi][ni][3] + b1);
        }
    }
}

// ---------------- fp32 SIMT GEMM (lin only) ---------------------------------
#define BM 128
#define BN 128
#define BK 8

__global__ void __launch_bounds__(256) sgemm_kernel(
    const float* __restrict__ A, int lda,
    const float* __restrict__ B, int ldb,
    float* __restrict__ C, int ldc, int K,
    const float* __restrict__ bias, int act)
{
    __shared__ float As[2][BK][BM];
    __shared__ float Bs[2][BK][BN];

    const int tid = threadIdx.x;
    const int brow = blockIdx.y, bcol = blockIdx.x;
    const float* Ab = A + (size_t)brow * BM * lda;
    const float* Bb = B + (size_t)bcol * BN * ldb;

    const int lrow = tid >> 1;
    const int lcol = (tid & 1) * 4;
    const int tm = (tid >> 4) * 8;
    const int tn = (tid & 15) * 8;

    float acc[8][8];
#pragma unroll
    for (int i = 0; i < 8; i++)
#pragma unroll
        for (int j = 0; j < 8; j++) acc[i][j] = 0.0f;

    float4 a0 = *(const float4*)(Ab + (size_t)lrow * lda + lcol);
    float4 b0 = *(const float4*)(Bb + (size_t)lrow * ldb + lcol);
    As[0][lcol + 0][lrow] = a0.x; As[0][lcol + 1][lrow] = a0.y;
    As[0][lcol + 2][lrow] = a0.z; As[0][lcol + 3][lrow] = a0.w;
    Bs[0][lcol + 0][lrow] = b0.x; Bs[0][lcol + 1][lrow] = b0.y;
    Bs[0][lcol + 2][lrow] = b0.z; Bs[0][lcol + 3][lrow] = b0.w;
    __syncthreads();

    const int nk = K / BK;
    int buf = 0;
    for (int kt = 0; kt < nk; kt++) {
        float4 an, bn;
        const bool more = (kt + 1 < nk);
        if (more) {
            an = *(const float4*)(Ab + (size_t)lrow * lda + (kt + 1) * BK + lcol);
            bn = *(const float4*)(Bb + (size_t)lrow * ldb + (kt + 1) * BK + lcol);
        }
#pragma unroll
        for (int k = 0; k < BK; k++) {
            float af[8], bf[8];
            *(float4*)(af)     = *(const float4*)(&As[buf][k][tm]);
            *(float4*)(af + 4) = *(const float4*)(&As[buf][k][tm + 4]);
            *(float4*)(bf)     = *(const float4*)(&Bs[buf][k][tn]);
            *(float4*)(bf + 4) = *(const float4*)(&Bs[buf][k][tn + 4]);
#pragma unroll
            for (int i = 0; i < 8; i++)
#pragma unroll
                for (int j = 0; j < 8; j++)
                    acc[i][j] = fmaf(af[i], bf[j], acc[i][j]);
        }
        if (more) {
            buf ^= 1;
            As[buf][lcol + 0][lrow] = an.x; As[buf][lcol + 1][lrow] = an.y;
            As[buf][lcol + 2][lrow] = an.z; As[buf][lcol + 3][lrow] = an.w;
            Bs[buf][lcol + 0][lrow] = bn.x; Bs[buf][lcol + 1][lrow] = bn.y;
            Bs[buf][lcol + 2][lrow] = bn.z; Bs[buf][lcol + 3][lrow] = bn.w;
            __syncthreads();
        }
    }

    const int m0 = brow * BM + tm;
    const int n0 = bcol * BN + tn;
#pragma unroll
    for (int i = 0; i < 8; i++) {
        float* crow = C + (size_t)(m0 + i) * ldc;
        float v[8];
#pragma unroll
        for (int j = 0; j < 8; j++) {
            float t = acc[i][j];
            if (bias) t += bias[n0 + j];
            if (act == 1) t = tanhf(t);
            v[j] = t;
        }
        *(float4*)(crow + n0)     = make_float4(v[0], v[1], v[2], v[3]);
        *(float4*)(crow + n0 + 4) = make_float4(v[4], v[5], v[6], v[7]);
    }
}

// ---------------- elementwise / conversion kernels --------------------------
__global__ void lin_split_kernel() {
    int idx = blockIdx.x * blockDim.x + threadIdx.x;  // 256*1024
    int b = idx >> 10, u = idx & 1023;
    float h = g_decin[b * 2048 + u];
    __nv_bfloat16 hi, lo; split_bf(h, hi, lo);
    g_h0hi[idx] = hi; g_h0lo[idx] = lo;
    g_dc[idx] = g_decin[b * 2048 + 1024 + u];
}

__global__ void split_decin_kernel() {
    int idx = blockIdx.x * blockDim.x + threadIdx.x;  // 4096*2048
    int r = idx >> 11, u = idx & 2047;
    float v = g_decin[idx];
    __nv_bfloat16 hi, lo; split_bf(v, hi, lo);
    g_dinhi[idx] = hi; g_dinlo[idx] = lo;
    if (u < 1024) {
        g_h0hi[r * 1024 + u] = hi;
        g_h0lo[r * 1024 + u] = lo;
    } else {
        g_dc[r * 1024 + (u - 1024)] = v;
    }
}

// permuted row: r_new -> orig row (gate*1024 + unit)
__device__ __forceinline__ int perm_orig(int r_new) {
    int cb = r_new >> 6, gate = (r_new >> 4) & 3, u4 = r_new & 15;
    return gate * 1024 + cb * 16 + u4;
}

__global__ void conv_w_kernel(const float* __restrict__ dec_Wih,
                              const float* __restrict__ dec_Whh) {
    int idx = blockIdx.x * blockDim.x + threadIdx.x;  // 4096*1536
    if (idx >= 4 * LHD * KW) return;
    int row = idx / KW, k = idx - row * KW;
    int orig = perm_orig(row);
    float v = (k < TT) ? dec_Wih[(size_t)orig * 2560 + 2048 + k]
                       : dec_Whh[(size_t)orig * 1024 + (k - TT)];
    __nv_bfloat16 hi, lo; split_bf(v, hi, lo);
    g_whi[idx] = hi; g_wlo[idx] = lo;
}

__global__ void conv_x_kernel(const float* __restrict__ x) {
    int idx = blockIdx.x * blockDim.x + threadIdx.x;
    float v = x[idx];
    __nv_bfloat16 hi, lo; split_bf(v, hi, lo);
    g_xhi[idx] = hi; g_xlo[idx] = lo;
}

__global__ void conv_cw_kernel(const float* __restrict__ w) {
    int idx = blockIdx.x * blockDim.x + threadIdx.x;  // 4096*1024
    int row = idx >> 10, k = idx & 1023;
    __nv_bfloat16 hi, lo; split_bf(w[(size_t)perm_orig(row) * 1024 + k], hi, lo);
    g_cwhi[idx] = hi; g_cwlo[idx] = lo;
}

__global__ void conv_wctx_kernel(const float* __restrict__ dec_Wih) {
    int idx = blockIdx.x * blockDim.x + threadIdx.x;  // 4096*2048
    int row = idx >> 11, k = idx & 2047;
    __nv_bfloat16 hi, lo; split_bf(dec_Wih[(size_t)perm_orig(row) * 2560 + k], hi, lo);
    g_wctxhi[idx] = hi; g_wctxlo[idx] = lo;
}

__global__ void conv_ow_kernel(const float* __restrict__ w) {
    int idx = blockIdx.x * blockDim.x + threadIdx.x;  // 512*1024
    __nv_bfloat16 hi, lo; split_bf(w[idx], hi, lo);
    g_owhi[idx] = hi; g_owlo[idx] = lo;
}

__global__ void conv_pw_kernel(const float* __restrict__ w) {
    int idx = blockIdx.x * blockDim.x + threadIdx.x;  // 2048*1024
    __nv_bfloat16 hi, lo; split_bf(w[idx], hi, lo);
    g_pwhi[idx] = hi; g_pwlo[idx] = lo;
}

__global__ void conv_bias_kernel(const float* __restrict__ dbih, const float* __restrict__ dbhh,
                                 const float* __restrict__ cbih, const float* __restrict__ cbhh) {
    int r = blockIdx.x * blockDim.x + threadIdx.x;   // 4096
    if (r >= 4096) return;
    int orig = perm_orig(r);
    g_pbdec[r]  = dbih[orig] + dbhh[orig];
    g_pbcond[r] = cbih[orig] + cbhh[orig];
}

// ---------------- launch ----------------------------------------------------
extern "C" void kernel_launch(void* const* d_in, const int* in_sizes, int n_in,
                              void* d_out, int out_size) {
    const float* z        = (const float*)d_in[0];
    const float* x        = (const float*)d_in[1];
    const float* lin_in_w = (const float*)d_in[2];
    const float* lin_in_b = (const float*)d_in[3];
    const float* cond_Whh = (const float*)d_in[5];
    const float* cond_bih = (const float*)d_in[6];
    const float* cond_bhh = (const float*)d_in[7];
    const float* pre_w    = (const float*)d_in[8];
    const float* pre_b    = (const float*)d_in[9];
    const float* dec_Wih  = (const float*)d_in[10];
    const float* dec_Whh  = (const float*)d_in[11];
    const float* dec_bih  = (const float*)d_in[12];
    const float* dec_bhh  = (const float*)d_in[13];
    const float* out_w    = (const float*)d_in[14];
    const float* out_b    = (const float*)d_in[15];
    float* out = (float*)d_out;

    float *pdecin, *pprectx, *pdc, *ppbdec, *ppbcond;
    __nv_bfloat16 *ph0hi, *ph0lo, *ph1hi, *ph1lo, *pwhi, *pwlo, *pcwhi, *pcwlo,
                  *pcohi, *pcolo, *pdinhi, *pdinlo, *pwctxhi, *pwctxlo,
                  *powhi, *powlo, *ppwhi, *ppwlo, *phisthi, *phistlo;
    cudaGetSymbolAddress((void**)&pdecin,  g_decin);
    cudaGetSymbolAddress((void**)&pprectx, g_prectx);
    cudaGetSymbolAddress((void**)&pdc,     g_dc);
    cudaGetSymbolAddress((void**)&ppbdec,  g_pbdec);
    cudaGetSymbolAddress((void**)&ppbcond, g_pbcond);
    cudaGetSymbolAddress((void**)&ph0hi,   g_h0hi);
    cudaGetSymbolAddress((void**)&ph0lo,   g_h0lo);
    cudaGetSymbolAddress((void**)&ph1hi,   g_h1hi);
    cudaGetSymbolAddress((void**)&ph1lo,   g_h1lo);
    cudaGetSymbolAddress((void**)&pwhi,    g_whi);
    cudaGetSymbolAddress((void**)&pwlo,    g_wlo);
    cudaGetSymbolAddress((void**)&pcwhi,   g_cwhi);
    cudaGetSymbolAddress((void**)&pcwlo,   g_cwlo);
    cudaGetSymbolAddress((void**)&pcohi,   g_cohi);
    cudaGetSymbolAddress((void**)&pcolo,   g_colo);
    cudaGetSymbolAddress((void**)&pdinhi,  g_dinhi);
    cudaGetSymbolAddress((void**)&pdinlo,  g_dinlo);
    cudaGetSymbolAddress((void**)&pwctxhi, g_wctxhi);
    cudaGetSymbolAddress((void**)&pwctxlo, g_wctxlo);
    cudaGetSymbolAddress((void**)&powhi,   g_owhi);
    cudaGetSymbolAddress((void**)&powlo,   g_owlo);
    cudaGetSymbolAddress((void**)&ppwhi,   g_pwhi);
    cudaGetSymbolAddress((void**)&ppwlo,   g_pwlo);
    cudaGetSymbolAddress((void**)&phisthi, g_histhi);
    cudaGetSymbolAddress((void**)&phistlo, g_histlo);

    const int MMA_SMEM = NSTAGE * STAGE_B;   // 81920
    cudaFuncSetAttribute(gemm_lstm_kernel, cudaFuncAttributeMaxDynamicSharedMemorySize, MMA_SMEM);
    cudaFuncSetAttribute(gemm3_kernel,     cudaFuncAttributeMaxDynamicSharedMemorySize, MMA_SMEM);

    // one-time conversions (weights permuted on the gate axis)
    conv_w_kernel<<<(4 * LHD * KW + 255) / 256, 256>>>(dec_Wih, dec_Whh);
    conv_x_kernel<<<(BB * SSS * NNN * TT) / 256, 256>>>(x);
    conv_cw_kernel<<<(4 * CHD * CHD) / 256, 256>>>(cond_Whh);
    conv_wctx_kernel<<<(4 * LHD * 2 * LHD) / 256, 256>>>(dec_Wih);
    conv_ow_kernel<<<(TT * LHD) / 256, 256>>>(out_w);
    conv_pw_kernel<<<(2 * LHD * CHD) / 256, 256>>>(pre_w);
    conv_bias_kernel<<<16, 256>>>(dec_bih, dec_bhh, cond_bih, cond_bhh);

    // hc0 = tanh(z @ lin_in_w^T + b)
    sgemm_kernel<<<dim3(2048 / BN, BB / BM), 256>>>(
        z, 512, lin_in_w, 512, pdecin, 2048, 512, lin_in_b, 1);
    lin_split_kernel<<<(BB * CHD) / 256, 256>>>();

    // cond LSTM: fused gates+cell, h ping-pong, history into g_co
    for (int s = 0; s < SSS; s++) {
        const __nv_bfloat16* ahi = (s & 1) ? ph1hi : ph0hi;
        const __nv_bfloat16* alo = (s & 1) ? ph1lo : ph0lo;
        __nv_bfloat16* whi_ = (s & 1) ? ph0hi : ph1hi;
        __nv_bfloat16* wlo_ = (s & 1) ? ph0lo : ph1lo;
        gemm_lstm_kernel<<<dim3(32, 2), 256, MMA_SMEM>>>(
            0, 1024, 0, ahi, alo, pcwhi, pcwlo, 1024,
            nullptr, ppbcond, pdc, whi_, wlo_, pcohi, pcolo, s * BB);
    }

    // dec_in = cond_outs @ pre_w^T + pre_b
    gemm3_kernel<<<dim3(16, 32), 256, MMA_SMEM>>>(
        pcohi, pcolo, 1024, ppwhi, ppwlo, 1024, pdecin, 2048, 1024, pre_b, 0);
    split_decin_kernel<<<(SB * 2 * LHD) / 256, 256>>>();

    // pre_ctx = dec_in @ W_ctx^T + (bih+bhh), permuted cols
    gemm3_kernel<<<dim3(32, 32), 256, MMA_SMEM>>>(
        pdinhi, pdinlo, 2048, pwctxhi, pwctxlo, 2048, pprectx, 4096, 2048, ppbdec, 0);

    // decoder loop: fused gates+cell, h history for batched out-proj
    for (int n = 0; n < NNN; n++) {
        const __nv_bfloat16* ahi = (n & 1) ? ph1hi : ph0hi;
        const __nv_bfloat16* alo = (n & 1) ? ph1lo : ph0lo;
        __nv_bfloat16* whi_ = (n & 1) ? ph0hi : ph1hi;
        __nv_bfloat16* wlo_ = (n & 1) ? ph0lo : ph1lo;
        if (n == 0) {
            gemm_lstm_kernel<<<dim3(32, 32), 256, MMA_SMEM>>>(
                n, 1024, 0, ahi, alo, pwhi + 512, pwlo + 512, KW,
                pprectx, nullptr, pdc, whi_, wlo_, phisthi, phistlo, 0);
        } else {
            gemm_lstm_kernel<<<dim3(32, 32), 256, MMA_SMEM>>>(
                n, KW, 1, ahi, alo, pwhi, pwlo, KW,
                pprectx, nullptr, pdc, whi_, wlo_, phisthi, phistlo, n * SB);
        }
    }

    // batched out-projection: hist (65536 x 1024) @ out_w^T + out_b, scatter
    gemm3_kernel<<<dim3(4, 512), 256, MMA_SMEM>>>(
        phisthi, phistlo, 1024, powhi, powlo, 1024, out, TT, 1024, out_b, 2);
}